// round 1
// baseline (speedup 1.0000x reference)
#include <cuda_runtime.h>
#include <cstdint>

// Problem constants
#define BATCH 4
#define CCH   256      // channels
#define HWPX  4096     // 64*64
#define MID   64

// ---------------- scratch (device globals: allocation-free rule) -------------
__device__ float g_T[BATCH * MID * HWPX];                    //  4 MB
__device__ float g_K[BATCH * CCH * HWPX];                    // 16 MB
__device__ float g_Q[BATCH * CCH * HWPX];                    // 16 MB
__device__ float g_V[BATCH * CCH * HWPX];                    // 16 MB
__device__ float g_P[(size_t)BATCH * HWPX * HWPX];           // 256 MB  P = exp(Et)
__device__ float g_Zpart[BATCH * 64 * HWPX];                 //  4 MB  partial row sums
__device__ float g_Zinv[BATCH * HWPX];                       // 64 KB

// ---------------------------------------------------------------------------
// 1) T[b,m,p] = relu( (w1[m]*inv[m]) * bm[b,p] + (bias[m]-mean[m]*inv[m]) )
//    bm = nearest-downsampled boundary map (src idx = 2*dst idx)
// ---------------------------------------------------------------------------
__global__ void key_mid_kernel(const float* __restrict__ bmap,
                               const float* __restrict__ w1,
                               const float* __restrict__ bnscale,
                               const float* __restrict__ bnbias,
                               const float* __restrict__ bnmean,
                               const float* __restrict__ bnvar)
{
    int idx = blockIdx.x * 256 + threadIdx.x;       // over BATCH*MID*HWPX
    int p = idx & (HWPX - 1);
    int m = (idx >> 12) & (MID - 1);
    int b = idx >> 18;
    float inv = bnscale[m] * rsqrtf(bnvar[m] + 1e-5f);
    float a   = w1[m] * inv;
    float bb  = bnbias[m] - bnmean[m] * inv;
    int y = p >> 6, x = p & 63;
    float s = bmap[b * 16384 + y * 256 + x * 2];    // boundary[b,0,2y,2x]
    g_T[idx] = fmaxf(fmaf(a, s, bb), 0.0f);
}

// ---------------------------------------------------------------------------
// 2) Shared-weight SGEMM: C[b] (256 x 4096) = W (256 x KD) * B[b] (KD x 4096)
//    mode 0: W=key_w2  (KD=64),  B=g_T, C=g_K
//    mode 1: W=query_w (KD=256), B=U,   C=g_Q
//    mode 2: W=value_w (KD=256), B=U,   C=g_V
// Tiling: BM=BN=64, BK=16, 256 threads, 4x4 microtile.
// ---------------------------------------------------------------------------
__global__ void __launch_bounds__(256) sgemm_w_kernel(const float* __restrict__ W,
                                                      const float* __restrict__ Uin,
                                                      int mode)
{
    const int N = HWPX;
    const int KD = (mode == 0) ? MID : CCH;
    int b = blockIdx.z;
    const float* Bp = ((mode == 0) ? g_T : Uin) + (size_t)b * KD * N;
    float* Cp = ((mode == 0) ? g_K : (mode == 1 ? g_Q : g_V)) + (size_t)b * CCH * N;

    int m0 = blockIdx.y * 64, n0 = blockIdx.x * 64;
    __shared__ float As[16][64];
    __shared__ float Bs[16][64];
    int tid = threadIdx.x;
    int tx = tid & 15, ty = tid >> 4;
    float acc[4][4] = {};

    for (int k0 = 0; k0 < KD; k0 += 16) {
        {   // A tile: rows m0..m0+63, cols k0..k0+15 (transposed into As[k][m])
            int row = tid >> 2, q = tid & 3;
            float4 a4 = *(const float4*)(W + (size_t)(m0 + row) * KD + k0 + q * 4);
            As[q * 4 + 0][row] = a4.x; As[q * 4 + 1][row] = a4.y;
            As[q * 4 + 2][row] = a4.z; As[q * 4 + 3][row] = a4.w;
        }
        {   // B tile: rows k0..k0+15, cols n0..n0+63
            int kk = tid >> 4, nn = (tid & 15) * 4;
            *(float4*)&Bs[kk][nn] = *(const float4*)(Bp + (size_t)(k0 + kk) * N + n0 + nn);
        }
        __syncthreads();
#pragma unroll
        for (int kk = 0; kk < 16; ++kk) {
            float4 av = *(const float4*)&As[kk][ty << 2];
            float4 bv = *(const float4*)&Bs[kk][tx << 2];
            float ar[4] = {av.x, av.y, av.z, av.w};
            float br[4] = {bv.x, bv.y, bv.z, bv.w};
#pragma unroll
            for (int r = 0; r < 4; ++r)
#pragma unroll
                for (int s = 0; s < 4; ++s)
                    acc[r][s] = fmaf(ar[r], br[s], acc[r][s]);
        }
        __syncthreads();
    }
#pragma unroll
    for (int r = 0; r < 4; ++r) {
        float4 o4 = make_float4(acc[r][0], acc[r][1], acc[r][2], acc[r][3]);
        *(float4*)(Cp + (size_t)(m0 + ty * 4 + r) * N + n0 + tx * 4) = o4;
    }
}

// ---------------------------------------------------------------------------
// 3) P[b,i,j] = exp( sum_c K[b,c,i] * Q[b,c,j] )   (energy transposed)
//    Also emits per-(row i, j-tile) partial sums into g_Zpart (deterministic).
// ---------------------------------------------------------------------------
__global__ void __launch_bounds__(256) energy_exp_kernel()
{
    const int N = HWPX, KD = CCH;
    int b = blockIdx.z;
    const float* Ap = g_K + (size_t)b * KD * N;   // A[i,c] = Ap[c*N + i]
    const float* Bp = g_Q + (size_t)b * KD * N;   // B[c,j]
    float* Pp = g_P + (size_t)b * N * N;

    int i0 = blockIdx.y * 64, j0 = blockIdx.x * 64;
    __shared__ float As[16][64];
    __shared__ float Bs[16][64];
    int tid = threadIdx.x;
    int tx = tid & 15, ty = tid >> 4;
    float acc[4][4] = {};

    for (int c0 = 0; c0 < KD; c0 += 16) {
        {   // A (already k-major in memory along i): coalesced float4 along i
            int cc = tid >> 4, ii = (tid & 15) * 4;
            *(float4*)&As[cc][ii] = *(const float4*)(Ap + (size_t)(c0 + cc) * N + i0 + ii);
        }
        {
            int kk = tid >> 4, nn = (tid & 15) * 4;
            *(float4*)&Bs[kk][nn] = *(const float4*)(Bp + (size_t)(c0 + kk) * N + j0 + nn);
        }
        __syncthreads();
#pragma unroll
        for (int kk = 0; kk < 16; ++kk) {
            float4 av = *(const float4*)&As[kk][ty << 2];
            float4 bv = *(const float4*)&Bs[kk][tx << 2];
            float ar[4] = {av.x, av.y, av.z, av.w};
            float br[4] = {bv.x, bv.y, bv.z, bv.w};
#pragma unroll
            for (int r = 0; r < 4; ++r)
#pragma unroll
                for (int s = 0; s < 4; ++s)
                    acc[r][s] = fmaf(ar[r], br[s], acc[r][s]);
        }
        __syncthreads();
    }

    float rs[4];
#pragma unroll
    for (int r = 0; r < 4; ++r) {
        float4 p;
        p.x = __expf(acc[r][0]); p.y = __expf(acc[r][1]);
        p.z = __expf(acc[r][2]); p.w = __expf(acc[r][3]);
        rs[r] = (p.x + p.y) + (p.z + p.w);
        *(float4*)(Pp + (size_t)(i0 + ty * 4 + r) * N + j0 + tx * 4) = p;
    }
    // reduce rs across the 16 tx lanes (fixed order -> deterministic)
#pragma unroll
    for (int off = 8; off > 0; off >>= 1) {
#pragma unroll
        for (int r = 0; r < 4; ++r)
            rs[r] += __shfl_xor_sync(0xffffffffu, rs[r], off);
    }
    if (tx == 0) {
#pragma unroll
        for (int r = 0; r < 4; ++r)
            g_Zpart[(size_t)(b * 64 + blockIdx.x) * HWPX + i0 + ty * 4 + r] = rs[r];
    }
}

// ---------------------------------------------------------------------------
// 4) Zinv[b,i] = 1 / sum_jt Zpart[b,jt,i]   (fixed order, coalesced)
// ---------------------------------------------------------------------------
__global__ void zinv_kernel()
{
    int t = blockIdx.x * 256 + threadIdx.x;   // 0 .. BATCH*HWPX-1
    int b = t >> 12;
    int i = t & (HWPX - 1);
    float s = 0.0f;
#pragma unroll
    for (int jt = 0; jt < 64; ++jt)
        s += g_Zpart[(size_t)(b * 64 + jt) * HWPX + i];
    g_Zinv[t] = 1.0f / s;
}

// ---------------------------------------------------------------------------
// 5) Out[b,c,j] = gamma * ( sum_i (V[b,c,i]*Zinv[b,i]) * P[b,i,j] ) + U[b,c,j]
// ---------------------------------------------------------------------------
__global__ void __launch_bounds__(256) out_kernel(const float* __restrict__ Uin,
                                                  const float* __restrict__ gammap,
                                                  float* __restrict__ Out)
{
    const int N = HWPX, KD = HWPX;
    int b = blockIdx.z;
    const float* Ap = g_V + (size_t)b * CCH * KD;
    const float* Bp = g_P + (size_t)b * (size_t)KD * N;
    const float* zi = g_Zinv + (size_t)b * KD;
    const float* Up = Uin + (size_t)b * CCH * N;
    float* Cp = Out + (size_t)b * CCH * N;
    float gamma = __ldg(gammap);

    int m0 = blockIdx.y * 64, n0 = blockIdx.x * 64;
    __shared__ float As[16][64];
    __shared__ float Bs[16][64];
    int tid = threadIdx.x;
    int tx = tid & 15, ty = tid >> 4;
    float acc[4][4] = {};

    for (int k0 = 0; k0 < KD; k0 += 16) {
        {   // A tile with per-k 1/Z scaling folded into the load
            int row = tid >> 2, q = tid & 3;
            float4 a4 = *(const float4*)(Ap + (size_t)(m0 + row) * KD + k0 + q * 4);
            float4 z4 = *(const float4*)(zi + k0 + q * 4);
            a4.x *= z4.x; a4.y *= z4.y; a4.z *= z4.z; a4.w *= z4.w;
            As[q * 4 + 0][row] = a4.x; As[q * 4 + 1][row] = a4.y;
            As[q * 4 + 2][row] = a4.z; As[q * 4 + 3][row] = a4.w;
        }
        {
            int kk = tid >> 4, nn = (tid & 15) * 4;
            *(float4*)&Bs[kk][nn] = *(const float4*)(Bp + (size_t)(k0 + kk) * N + n0 + nn);
        }
        __syncthreads();
#pragma unroll
        for (int kk = 0; kk < 16; ++kk) {
            float4 av = *(const float4*)&As[kk][ty << 2];
            float4 bv = *(const float4*)&Bs[kk][tx << 2];
            float ar[4] = {av.x, av.y, av.z, av.w};
            float br[4] = {bv.x, bv.y, bv.z, bv.w};
#pragma unroll
            for (int r = 0; r < 4; ++r)
#pragma unroll
                for (int s = 0; s < 4; ++s)
                    acc[r][s] = fmaf(ar[r], br[s], acc[r][s]);
        }
        __syncthreads();
    }
#pragma unroll
    for (int r = 0; r < 4; ++r) {
        size_t off = (size_t)(m0 + ty * 4 + r) * N + n0 + tx * 4;
        float4 u4 = *(const float4*)(Up + off);
        float4 o4;
        o4.x = fmaf(gamma, acc[r][0], u4.x);
        o4.y = fmaf(gamma, acc[r][1], u4.y);
        o4.z = fmaf(gamma, acc[r][2], u4.z);
        o4.w = fmaf(gamma, acc[r][3], u4.w);
        *(float4*)(Cp + off) = o4;
    }
}

// ---------------------------------------------------------------------------
extern "C" void kernel_launch(void* const* d_in, const int* in_sizes, int n_in,
                              void* d_out, int out_size)
{
    const float* bmap     = (const float*)d_in[0];
    const float* U        = (const float*)d_in[1];
    const float* key_w1   = (const float*)d_in[2];
    const float* bn_scale = (const float*)d_in[3];
    const float* bn_bias  = (const float*)d_in[4];
    const float* bn_mean  = (const float*)d_in[5];
    const float* bn_var   = (const float*)d_in[6];
    const float* key_w2   = (const float*)d_in[7];
    const float* query_w  = (const float*)d_in[8];
    const float* value_w  = (const float*)d_in[9];
    const float* gamma    = (const float*)d_in[10];
    float* out = (float*)d_out;

    // 1) mid activations for the key path
    key_mid_kernel<<<(BATCH * MID * HWPX) / 256, 256>>>(bmap, key_w1, bn_scale,
                                                        bn_bias, bn_mean, bn_var);
    // 2) K = key_w2 @ T ; Q = query_w @ U ; V = value_w @ U
    sgemm_w_kernel<<<dim3(64, 4, BATCH), 256>>>(key_w2,  nullptr, 0);
    sgemm_w_kernel<<<dim3(64, 4, BATCH), 256>>>(query_w, U,       1);
    sgemm_w_kernel<<<dim3(64, 4, BATCH), 256>>>(value_w, U,       2);
    // 3) P = exp(K^T Q) + partial row sums
    energy_exp_kernel<<<dim3(64, 64, BATCH), 256>>>();
    // 4) Zinv
    zinv_kernel<<<(BATCH * HWPX) / 256, 256>>>();
    // 5) final output
    out_kernel<<<dim3(64, 4, BATCH), 256>>>(U, gamma, out);
}